// round 10
// baseline (speedup 1.0000x reference)
#include <cuda_runtime.h>
#include <cstdint>
#include <cstddef>

#define BATCH   4096
#define FFI     64
#define DDIM    256
#define PAIRS   2016
#define KC      16                 // K elements per chunk
#define NCH     (DDIM / KC)        // 16 chunks per batch
#define SROW    24                 // padded row stride (words): conflict-free phases
#define STAGE_WORDS (FFI * SROW)   // 1536 words = 6144 B
#define WARPS   4
#define THREADS (WARPS * 32)
#define NCTA    592                // ~4 per SM; atomic queue self-balances
#define SMEM_BYTES (WARPS * 2 * STAGE_WORDS * 4)   // 49152

// 20 upper-triangular m16n8 tiles of the 64x64 gram; one warp does all 20.
__device__ constexpr int tMI[20] = {0,0,0,0,0,0,0,0, 1,1,1,1,1,1, 2,2,2,2, 3,3};
__device__ constexpr int tNJ[20] = {0,1,2,3,4,5,6,7, 2,3,4,5,6,7, 4,5,6,7, 6,7};

__device__ unsigned g_ctr;

__global__ void reset_ctr() { g_ctr = 0u; }

__device__ __forceinline__ uint32_t f2tf32(float x) {
    uint32_t r;
    asm("cvt.rna.tf32.f32 %0, %1;" : "=r"(r) : "f"(x));
    return r;
}

__device__ __forceinline__ void mma8(float& d0, float& d1, float& d2, float& d3,
                                     uint32_t a0, uint32_t a1, uint32_t a2, uint32_t a3,
                                     uint32_t b0, uint32_t b1) {
    asm("mma.sync.aligned.m16n8k8.row.col.f32.tf32.tf32.f32 "
        "{%0,%1,%2,%3}, {%4,%5,%6,%7}, {%8,%9}, {%0,%1,%2,%3};"
        : "+f"(d0), "+f"(d1), "+f"(d2), "+f"(d3)
        : "r"(a0), "r"(a1), "r"(a2), "r"(a3), "r"(b0), "r"(b1));
}

__device__ __forceinline__ void cp_async16(uint32_t dst_smem, const void* src) {
    asm volatile("cp.async.cg.shared.global [%0], [%1], 16;"
                 :: "r"(dst_smem), "l"(src) : "memory");
}
__device__ __forceinline__ void cp_commit() {
    asm volatile("cp.async.commit_group;" ::: "memory");
}
__device__ __forceinline__ void cp_wait1() {
    asm volatile("cp.async.wait_group 1;" ::: "memory");
}

// Issue one KC-wide chunk of batch t into this warp's stage. Predicated off
// for invalid t; ALWAYS commits (empty groups keep wait accounting uniform).
__device__ __forceinline__ void issue_chunk(const float* __restrict__ in,
                                            unsigned t, int chunk,
                                            uint32_t dst, int lane) {
    if (t < BATCH) {
        const float* src = in + (size_t)t * (FFI * DDIM) + chunk * KC;
#pragma unroll
        for (int i = 0; i < 8; i++) {
            const int idx = lane + 32 * i;
            const int r = idx >> 2, c4 = idx & 3;     // 4 float4 per row
            cp_async16(dst + (uint32_t)((r * SROW + c4 * 4) * 4),
                       src + (size_t)r * DDIM + c4 * 4);
        }
    }
    cp_commit();
}

// One KC=16 chunk: 2 k8-steps. Per step, each of the 8 row-groups is loaded
// ONCE (8 conflict-free LDS.64), cvt.rna'd to tf32, and feeds all 20 MMAs.
// k-slot pairing (2q, 2q+1) is valid because A and B alias the same words
// with the same lane mapping (C = A*A^T), so the k-sum is order-invariant.
__device__ __forceinline__ void chunk_mma(const uint32_t* __restrict__ sbase,
                                          int lid, float (&acc)[80]) {
    const int grp = lid >> 2, quad = lid & 3;
    const uint32_t* base = sbase + grp * SROW + 2 * quad;
#pragma unroll
    for (int ks = 0; ks < KC / 8; ks++) {
        uint32_t c[8][2];
#pragma unroll
        for (int g = 0; g < 8; g++) {
            uint2 v = *reinterpret_cast<const uint2*>(base + g * 8 * SROW + ks * 8);
            c[g][0] = f2tf32(__uint_as_float(v.x));
            c[g][1] = f2tf32(__uint_as_float(v.y));
        }
#pragma unroll
        for (int t = 0; t < 20; t++) {
            const int a = 2 * tMI[t], b = tNJ[t];
            mma8(acc[4 * t], acc[4 * t + 1], acc[4 * t + 2], acc[4 * t + 3],
                 c[a][0], c[a + 1][0], c[a][1], c[a + 1][1],
                 c[b][0], c[b][1]);
        }
    }
}

__device__ __forceinline__ void stp(float* __restrict__ ob, int i, int j,
                                    float v, bool need_check) {
    if (!need_check || j > i)
        ob[i * FFI - (i * (i + 1)) / 2 + j - i - 1] = v;
}

__device__ __forceinline__ void epilogue(const float (&acc)[80], int lid,
                                         float* __restrict__ ob) {
    const int grp = lid >> 2, quad = lid & 3;
#pragma unroll
    for (int t = 0; t < 20; t++) {
        const int mi = tMI[t], nj = tNJ[t];
        const bool chk = (nj < 2 * mi + 2);
        const int i0 = mi * 16 + grp, i1 = i0 + 8;
        const int j0 = nj * 8 + 2 * quad, j1 = j0 + 1;
        stp(ob, i0, j0, acc[4 * t + 0], chk);
        stp(ob, i0, j1, acc[4 * t + 1], chk);
        stp(ob, i1, j0, acc[4 * t + 2], chk);
        stp(ob, i1, j1, acc[4 * t + 3], chk);
    }
}

__global__ void __launch_bounds__(THREADS, 4)
gram_warp_kernel(const float* __restrict__ in, float* __restrict__ out) {
    extern __shared__ uint32_t smem[];
    const int tid = threadIdx.x;
    const int wid = tid >> 5, lid = tid & 31;

    const uint32_t* sw = smem + wid * 2 * STAGE_WORDS;       // generic, reads
    uint32_t swb;                                            // shared addr, cp.async
    asm("{ .reg .u64 t; cvta.to.shared.u64 t, %1; cvt.u32.u64 %0, t; }"
        : "=r"(swb) : "l"(sw));

    // grab first batch and prime a 2-deep pipeline
    unsigned t = 0;
    if (lid == 0) t = atomicAdd(&g_ctr, 1u);
    t = __shfl_sync(0xffffffffu, t, 0);
    issue_chunk(in, t, 0, swb, lid);
    issue_chunk(in, t, 1, swb + STAGE_WORDS * 4, lid);

    while (t < BATCH) {
        float acc[80];
#pragma unroll
        for (int i = 0; i < 80; i++) acc[i] = 0.0f;

        unsigned tn = 0xffffffffu;
        for (int c = 0; c < NCH; c++) {
            cp_wait1();                 // pending {c, c+1} -> chunk c ready
            __syncwarp();
            chunk_mma(sw + (c & 1) * STAGE_WORDS, lid, acc);
            __syncwarp();               // all lanes done reading this stage
            if (c < NCH - 2) {
                issue_chunk(in, t, c + 2, swb + (c & 1) * STAGE_WORDS * 4, lid);
            } else if (c == NCH - 2) {
                // grab next batch; its chunk 0 reuses stage 0 (c&1 == 0)
                if (lid == 0) tn = atomicAdd(&g_ctr, 1u);
                tn = __shfl_sync(0xffffffffu, tn, 0);
                issue_chunk(in, tn, 0, swb, lid);
            } else {                    // c == NCH-1: next batch chunk 1
                issue_chunk(in, tn, 1, swb + STAGE_WORDS * 4, lid);
            }
        }

        epilogue(acc, lid, out + (size_t)t * PAIRS);  // overlaps next-batch loads
        t = tn;
    }
}

extern "C" void kernel_launch(void* const* d_in, const int* in_sizes, int n_in,
                              void* d_out, int out_size) {
    const float* in = (const float*)d_in[0];
    float* out = (float*)d_out;
    (void)in_sizes; (void)n_in; (void)out_size;

    cudaFuncSetAttribute(gram_warp_kernel,
                         cudaFuncAttributeMaxDynamicSharedMemorySize,
                         SMEM_BYTES);

    reset_ctr<<<1, 1>>>();
    gram_warp_kernel<<<NCTA, THREADS, SMEM_BYTES>>>(in, out);
}

// round 12
// speedup vs baseline: 1.0638x; 1.0638x over previous
#include <cuda_runtime.h>
#include <cstdint>
#include <cstddef>

#define BATCH   4096
#define FFI     64
#define DDIM    256
#define PAIRS   2016
#define THREADS 128
#define KC      32            // K elements per chunk
#define NCH     (DDIM / KC)   // 8
#define SROW    40            // padded smem row stride (words), ==8 mod 32

// per-warp tiles: 20 upper-triangular m16n8 tiles, 5 per warp.
// cTMI/cTNJ: tile (m-strip, n-tile). cMASK: union of 8-row groups a warp
// must touch per ks (A strips use groups {2mi,2mi+1}, B tiles group {nj};
// B frags alias A raw words since both operands are the same matrix).
__device__ constexpr int cTMI[4][5] = {{0,0,0,0,0},{0,0,0,1,1},{1,1,1,1,2},{2,2,2,3,3}};
__device__ constexpr int cTNJ[4][5] = {{0,1,2,3,4},{5,6,7,2,3},{4,5,6,7,4},{5,6,7,6,7}};
__device__ constexpr unsigned cMASK[4] = {0x1Fu, 0xEFu, 0xFCu, 0xF0u};

__device__ __forceinline__ uint32_t f2tf32(float x) {
    uint32_t r;
    asm("cvt.rna.tf32.f32 %0, %1;" : "=r"(r) : "f"(x));
    return r;
}

__device__ __forceinline__ void mma8(float& d0, float& d1, float& d2, float& d3,
                                     uint32_t a0, uint32_t a1, uint32_t a2, uint32_t a3,
                                     uint32_t b0, uint32_t b1) {
    asm("mma.sync.aligned.m16n8k8.row.col.f32.tf32.tf32.f32 "
        "{%0,%1,%2,%3}, {%4,%5,%6,%7}, {%8,%9}, {%0,%1,%2,%3};"
        : "+f"(d0), "+f"(d1), "+f"(d2), "+f"(d3)
        : "r"(a0), "r"(a1), "r"(a2), "r"(a3), "r"(b0), "r"(b1));
}

// k-permutation trick (see R7): lane k-slots (2q, 2q+1) instead of (q, q+4).
// Valid because A and B fragments alias the SAME smem words with the SAME
// lane mapping (C = A*A^T), so the accumulated k-sum is unchanged.
template <int W>
__device__ __forceinline__ void chunk_mma(const uint32_t* __restrict__ sb,
                                          int lid, float (&acc)[20]) {
    const int grp = lid >> 2, quad = lid & 3;
    const uint32_t* base = sb + grp * SROW + 2 * quad;
#pragma unroll
    for (int ks = 0; ks < KC / 8; ks++) {
        const int k = ks * 8;
        uint32_t c[8][2];
#pragma unroll
        for (int g = 0; g < 8; g++) {
            if (cMASK[W] & (1u << g)) {
                uint2 v = *reinterpret_cast<const uint2*>(base + g * 8 * SROW + k);
                c[g][0] = v.x; c[g][1] = v.y;
            }
        }
#pragma unroll
        for (int t = 0; t < 5; t++) {
            const int mi = cTMI[W][t];
            const int nj = cTNJ[W][t];
            mma8(acc[4 * t], acc[4 * t + 1], acc[4 * t + 2], acc[4 * t + 3],
                 c[2 * mi][0], c[2 * mi + 1][0], c[2 * mi][1], c[2 * mi + 1][1],
                 c[nj][0], c[nj][1]);
        }
    }
}

__device__ __forceinline__ void stp(float* __restrict__ ob, int i, int j,
                                    float v, bool need_check) {
    if (!need_check || j > i)
        ob[i * FFI - (i * (i + 1)) / 2 + j - i - 1] = v;
}

template <int W>
__device__ __forceinline__ void epilogue(const float (&acc)[20], int lid,
                                         float* __restrict__ ob) {
    const int grp = lid >> 2, quad = lid & 3;
#pragma unroll
    for (int t = 0; t < 5; t++) {
        const int mi = cTMI[W][t];
        const int nj = cTNJ[W][t];
        const bool chk = (nj < 2 * mi + 2);   // tile straddles the diagonal
        const int i0 = mi * 16 + grp, i1 = i0 + 8;
        const int j0 = nj * 8 + 2 * quad, j1 = j0 + 1;
        stp(ob, i0, j0, acc[4 * t + 0], chk);
        stp(ob, i0, j1, acc[4 * t + 1], chk);
        stp(ob, i1, j0, acc[4 * t + 2], chk);
        stp(ob, i1, j1, acc[4 * t + 3], chk);
    }
}

__global__ void __launch_bounds__(THREADS, 6)
gram_mma_kernel(const float* __restrict__ in, float* __restrict__ out) {
    __shared__ __align__(16) uint32_t sb[2][FFI * SROW];   // 20480 B

    const int tid = threadIdx.x;
    const int wid = tid >> 5, lid = tid & 31;
    const int b = blockIdx.x;

    const float4* src = reinterpret_cast<const float4*>(in)
                        + (size_t)b * FFI * (DDIM / 4);

    // loader mapping: iteration i covers quad-index idx = tid + 128*i;
    // row r = idx>>3 (0..63), float4-column c4 = idx&7 within the chunk.
    float4 regs[4];
    auto load_chunk = [&](int c) {
#pragma unroll
        for (int i = 0; i < 4; i++) {
            const int idx = tid + THREADS * i;
            const int r = idx >> 3, c4 = idx & 7;
            regs[i] = __ldg(src + (size_t)r * (DDIM / 4) + c * (KC / 4) + c4);
        }
    };
    auto store_chunk = [&](int buf) {
#pragma unroll
        for (int i = 0; i < 4; i++) {
            const int idx = tid + THREADS * i;
            const int r = idx >> 3, c4 = idx & 7;
            uint4 v;
            v.x = f2tf32(regs[i].x); v.y = f2tf32(regs[i].y);
            v.z = f2tf32(regs[i].z); v.w = f2tf32(regs[i].w);
            *reinterpret_cast<uint4*>(&sb[buf][r * SROW + c4 * 4]) = v;
        }
    };

    float acc[20];
#pragma unroll
    for (int i = 0; i < 20; i++) acc[i] = 0.0f;

    // single barrier per chunk: a warp passing sync(c) implies all warps
    // finished mma(c-1), so the same-buffer store two iterations later is safe.
    load_chunk(0);
    for (int c = 0; c < NCH; c++) {
        store_chunk(c & 1);
        __syncthreads();
        if (c + 1 < NCH) load_chunk(c + 1);
        const uint32_t* buf = sb[c & 1];
        switch (wid) {
            case 0:  chunk_mma<0>(buf, lid, acc); break;
            case 1:  chunk_mma<1>(buf, lid, acc); break;
            case 2:  chunk_mma<2>(buf, lid, acc); break;
            default: chunk_mma<3>(buf, lid, acc); break;
        }
    }

    float* ob = out + (size_t)b * PAIRS;
    switch (wid) {
        case 0:  epilogue<0>(acc, lid, ob); break;
        case 1:  epilogue<1>(acc, lid, ob); break;
        case 2:  epilogue<2>(acc, lid, ob); break;
        default: epilogue<3>(acc, lid, ob); break;
    }
}

extern "C" void kernel_launch(void* const* d_in, const int* in_sizes, int n_in,
                              void* d_out, int out_size) {
    const float* in = (const float*)d_in[0];
    float* out = (float*)d_out;
    (void)in_sizes; (void)n_in; (void)out_size;
    gram_mma_kernel<<<BATCH, THREADS>>>(in, out);
}

// round 13
// speedup vs baseline: 1.1013x; 1.0352x over previous
#include <cuda_runtime.h>
#include <cstdint>
#include <cstddef>

#define BATCH   4096
#define FFI     64
#define DDIM    256
#define PAIRS   2016
#define THREADS 64
#define KC      32                // K elements per chunk
#define NCH     (DDIM / KC)       // 8
#define SROW    40                // padded row stride (words), ==8 mod 32
#define BUF_WORDS (FFI * SROW)    // 2560 words per buffer

// 20 upper-triangular m16n8 tiles of the 64x64 gram; EACH warp does all 20
// (warps split k instead of tiles -> every smem word fragment-loaded once).
__device__ constexpr int tMI[20] = {0,0,0,0,0,0,0,0, 1,1,1,1,1,1, 2,2,2,2, 3,3};
__device__ constexpr int tNJ[20] = {0,1,2,3,4,5,6,7, 2,3,4,5,6,7, 4,5,6,7, 6,7};

__device__ __forceinline__ uint32_t f2tf32(float x) {
    uint32_t r;
    asm("cvt.rna.tf32.f32 %0, %1;" : "=r"(r) : "f"(x));
    return r;
}

__device__ __forceinline__ void mma8(float& d0, float& d1, float& d2, float& d3,
                                     uint32_t a0, uint32_t a1, uint32_t a2, uint32_t a3,
                                     uint32_t b0, uint32_t b1) {
    asm("mma.sync.aligned.m16n8k8.row.col.f32.tf32.tf32.f32 "
        "{%0,%1,%2,%3}, {%4,%5,%6,%7}, {%8,%9}, {%0,%1,%2,%3};"
        : "+f"(d0), "+f"(d1), "+f"(d2), "+f"(d3)
        : "r"(a0), "r"(a1), "r"(a2), "r"(a3), "r"(b0), "r"(b1));
}

__device__ __forceinline__ void cp_async16(uint32_t dst, const void* src) {
    asm volatile("cp.async.cg.shared.global [%0], [%1], 16;"
                 :: "r"(dst), "l"(src) : "memory");
}
__device__ __forceinline__ void cp_commit() {
    asm volatile("cp.async.commit_group;" ::: "memory");
}
__device__ __forceinline__ void cp_wait1() {
    asm volatile("cp.async.wait_group 1;" ::: "memory");
}

__global__ void __launch_bounds__(THREADS, 8)
gram_ksplit_kernel(const float* __restrict__ in, float* __restrict__ out) {
    __shared__ __align__(16) uint32_t sb[2][BUF_WORDS];   // 20480 B

    const int tid = threadIdx.x;
    const int wid = tid >> 5, lid = tid & 31;
    const int b = blockIdx.x;

    const float* src = in + (size_t)b * (FFI * DDIM);
    uint32_t s0;
    asm("{ .reg .u64 t; cvta.to.shared.u64 t, %1; cvt.u32.u64 %0, t; }"
        : "=r"(s0) : "l"((const void*)sb));

    // issue one KC-chunk via cp.async (always commits; empty groups keep the
    // wait_group accounting uniform past the end of the batch).
    auto issue = [&](int c) {
        if (c < NCH) {
            const uint32_t dst = s0 + (uint32_t)((c & 1) * BUF_WORDS * 4);
            const float* sc = src + c * KC;
#pragma unroll
            for (int i = 0; i < 8; i++) {
                const int idx = tid + THREADS * i;
                const int r = idx >> 3, c4 = idx & 7;   // row, float4-col
                cp_async16(dst + (uint32_t)((r * SROW + c4 * 4) * 4),
                           sc + (size_t)r * DDIM + c4 * 4);
            }
        }
        cp_commit();
    };

    float acc[80];
#pragma unroll
    for (int i = 0; i < 80; i++) acc[i] = 0.0f;

    const int grp = lid >> 2, quad = lid & 3;

    issue(0);
    issue(1);
    for (int c = 0; c < NCH; c++) {
        cp_wait1();            // chunk c complete (this thread's copies)
        __syncthreads();       // all threads' copies visible

        // warp w handles ks-steps {2w, 2w+1} of this chunk. Per step: each of
        // the 8 row-groups loaded ONCE (conflict-free LDS.64), cvt.rna to
        // tf32, feeds all 20 MMAs. Lane k-slots (2q, 2q+1) are a k-permutation
        // applied identically to A and B (same words, same mapping), so the
        // accumulated k-sum is unchanged (C = A*A^T).
        const uint32_t* base = sb[c & 1] + grp * SROW + 2 * quad;
#pragma unroll
        for (int s = 0; s < 2; s++) {
            const int k = wid * 16 + s * 8;
            uint32_t cc[8][2];
#pragma unroll
            for (int g = 0; g < 8; g++) {
                uint2 v = *reinterpret_cast<const uint2*>(base + g * 8 * SROW + k);
                cc[g][0] = f2tf32(__uint_as_float(v.x));
                cc[g][1] = f2tf32(__uint_as_float(v.y));
            }
#pragma unroll
            for (int t = 0; t < 20; t++) {
                const int a = 2 * tMI[t], bj = tNJ[t];
                mma8(acc[4 * t], acc[4 * t + 1], acc[4 * t + 2], acc[4 * t + 3],
                     cc[a][0], cc[a + 1][0], cc[a][1], cc[a + 1][1],
                     cc[bj][0], cc[bj][1]);
            }
        }

        __syncthreads();       // all reads of buf (c&1) done before rewrite
        issue(c + 2);
    }

    // ---- 2-way cross-warp reduction, staged in the dead tile buffers ----
    float* s_red = reinterpret_cast<float*>(sb);       // [2][2048]
    float* rw = s_red + wid * 2048;
#pragma unroll
    for (int t = 0; t < 20; t++) {
        const int mi = tMI[t], nj = tNJ[t];
        const bool chk = (nj < 2 * mi + 2);            // straddles diagonal
        const int i0 = mi * 16 + grp, i1 = i0 + 8;
        const int j0 = nj * 8 + 2 * quad, j1 = j0 + 1;
        // p(i,j) = i*64 - i(i+1)/2 + j - i - 1 (strict-upper linear index)
        const int b0 = i0 * 64 - ((i0 * (i0 + 1)) >> 1) - i0 - 1;
        const int b1 = i1 * 64 - ((i1 * (i1 + 1)) >> 1) - i1 - 1;
        if (!chk || j0 > i0) rw[b0 + j0] = acc[4 * t + 0];
        if (!chk || j1 > i0) rw[b0 + j1] = acc[4 * t + 1];
        if (!chk || j0 > i1) rw[b1 + j0] = acc[4 * t + 2];
        if (!chk || j1 > i1) rw[b1 + j1] = acc[4 * t + 3];
    }
    __syncthreads();

    float* ob = out + (size_t)b * PAIRS;
#pragma unroll 1
    for (int p = tid; p < PAIRS; p += THREADS)
        ob[p] = s_red[p] + s_red[2048 + p];
}

extern "C" void kernel_launch(void* const* d_in, const int* in_sizes, int n_in,
                              void* d_out, int out_size) {
    const float* in = (const float*)d_in[0];
    float* out = (float*)d_out;
    (void)in_sizes; (void)n_in; (void)out_size;
    gram_ksplit_kernel<<<BATCH, THREADS>>>(in, out);
}

// round 14
// speedup vs baseline: 1.1468x; 1.0413x over previous
#include <cuda_runtime.h>
#include <cstdint>
#include <cstddef>

#define BATCH   4096
#define FFI     64
#define DDIM    256
#define PAIRS   2016
#define THREADS 128
#define KC      64            // K elements per chunk
#define NCH     (DDIM / KC)   // 4
#define SROW    72            // padded smem row stride (words), ==8 mod 32

// per-warp tiles: 20 upper-triangular m16n8 tiles, 5 per warp.
// cTMI/cTNJ: tile (m-strip, n-tile). cMASK: union of 8-row groups a warp
// must touch per ks (A strips use groups {2mi,2mi+1}, B tiles group {nj};
// B frags alias A raw words since both operands are the same matrix).
__device__ constexpr int cTMI[4][5] = {{0,0,0,0,0},{0,0,0,1,1},{1,1,1,1,2},{2,2,2,3,3}};
__device__ constexpr int cTNJ[4][5] = {{0,1,2,3,4},{5,6,7,2,3},{4,5,6,7,4},{5,6,7,6,7}};
__device__ constexpr unsigned cMASK[4] = {0x1Fu, 0xEFu, 0xFCu, 0xF0u};

__device__ __forceinline__ uint32_t f2tf32(float x) {
    uint32_t r;
    asm("cvt.rna.tf32.f32 %0, %1;" : "=r"(r) : "f"(x));
    return r;
}

__device__ __forceinline__ void mma8(float& d0, float& d1, float& d2, float& d3,
                                     uint32_t a0, uint32_t a1, uint32_t a2, uint32_t a3,
                                     uint32_t b0, uint32_t b1) {
    asm("mma.sync.aligned.m16n8k8.row.col.f32.tf32.tf32.f32 "
        "{%0,%1,%2,%3}, {%4,%5,%6,%7}, {%8,%9}, {%0,%1,%2,%3};"
        : "+f"(d0), "+f"(d1), "+f"(d2), "+f"(d3)
        : "r"(a0), "r"(a1), "r"(a2), "r"(a3), "r"(b0), "r"(b1));
}

// k-permutation trick: lane k-slots (2q, 2q+1) instead of (q, q+4).
// Valid because A and B fragments alias the SAME smem words with the SAME
// lane mapping (C = A*A^T), so the accumulated k-sum is unchanged.
template <int W>
__device__ __forceinline__ void chunk_mma(const uint32_t* __restrict__ sb,
                                          int lid, float (&acc)[20]) {
    const int grp = lid >> 2, quad = lid & 3;
    const uint32_t* base = sb + grp * SROW + 2 * quad;
#pragma unroll
    for (int ks = 0; ks < KC / 8; ks++) {
        const int k = ks * 8;
        uint32_t c[8][2];
#pragma unroll
        for (int g = 0; g < 8; g++) {
            if (cMASK[W] & (1u << g)) {
                uint2 v = *reinterpret_cast<const uint2*>(base + g * 8 * SROW + k);
                c[g][0] = v.x; c[g][1] = v.y;
            }
        }
#pragma unroll
        for (int t = 0; t < 5; t++) {
            const int mi = cTMI[W][t];
            const int nj = cTNJ[W][t];
            mma8(acc[4 * t], acc[4 * t + 1], acc[4 * t + 2], acc[4 * t + 3],
                 c[2 * mi][0], c[2 * mi + 1][0], c[2 * mi][1], c[2 * mi + 1][1],
                 c[nj][0], c[nj][1]);
        }
    }
}

// stage one value at triangle-packed index p(i,j) in smem
__device__ __forceinline__ void stg_pack(float* __restrict__ s_red, int i, int j,
                                         float v, bool need_check) {
    if (!need_check || j > i)
        s_red[i * FFI - (i * (i + 1)) / 2 + j - i - 1] = v;
}

template <int W>
__device__ __forceinline__ void stage_out(const float (&acc)[20], int lid,
                                          float* __restrict__ s_red) {
    const int grp = lid >> 2, quad = lid & 3;
#pragma unroll
    for (int t = 0; t < 5; t++) {
        const int mi = cTMI[W][t];
        const int nj = cTNJ[W][t];
        const bool chk = (nj < 2 * mi + 2);   // tile straddles the diagonal
        const int i0 = mi * 16 + grp, i1 = i0 + 8;
        const int j0 = nj * 8 + 2 * quad, j1 = j0 + 1;
        stg_pack(s_red, i0, j0, acc[4 * t + 0], chk);
        stg_pack(s_red, i0, j1, acc[4 * t + 1], chk);
        stg_pack(s_red, i1, j0, acc[4 * t + 2], chk);
        stg_pack(s_red, i1, j1, acc[4 * t + 3], chk);
    }
}

__global__ void __launch_bounds__(THREADS, 5)
gram_mma_kernel(const float* __restrict__ in, float* __restrict__ out) {
    __shared__ __align__(16) uint32_t sb[2][FFI * SROW];   // 36864 B

    const int tid = threadIdx.x;
    const int wid = tid >> 5, lid = tid & 31;
    const int b = blockIdx.x;

    const float4* src = reinterpret_cast<const float4*>(in)
                        + (size_t)b * FFI * (DDIM / 4);
    const int lrow = tid >> 4;      // 0..7 row-within-group-of-8
    const int lcol = tid & 15;      // float4 column within chunk

    float4 regs[8];
    auto load_chunk = [&](int c) {
#pragma unroll
        for (int i = 0; i < 8; i++) {
            const int r = i * 8 + lrow;
            regs[i] = __ldg(src + (size_t)r * (DDIM / 4) + c * (KC / 4) + lcol);
        }
    };
    auto store_chunk = [&](int buf) {
#pragma unroll
        for (int i = 0; i < 8; i++) {
            const int r = i * 8 + lrow;
            uint4 v;
            v.x = f2tf32(regs[i].x); v.y = f2tf32(regs[i].y);
            v.z = f2tf32(regs[i].z); v.w = f2tf32(regs[i].w);
            *reinterpret_cast<uint4*>(&sb[buf][r * SROW + lcol * 4]) = v;
        }
    };

    float acc[20];
#pragma unroll
    for (int i = 0; i < 20; i++) acc[i] = 0.0f;

    // single barrier per chunk: a warp passing sync(c) implies all warps
    // finished mma(c-1), so the same-buffer store two iterations later is safe.
    load_chunk(0);
    for (int c = 0; c < NCH; c++) {
        store_chunk(c & 1);
        __syncthreads();
        if (c + 1 < NCH) load_chunk(c + 1);
        const uint32_t* buf = sb[c & 1];
        switch (wid) {
            case 0:  chunk_mma<0>(buf, lid, acc); break;
            case 1:  chunk_mma<1>(buf, lid, acc); break;
            case 2:  chunk_mma<2>(buf, lid, acc); break;
            default: chunk_mma<3>(buf, lid, acc); break;
        }
    }

    // ---- epilogue: triangle-packed staging in sb[0] (its last reader was
    // chunk 2, which all warps finished before the chunk-3 barrier), then a
    // fully coalesced copy to gmem. Kills scattered-STG write amplification.
    float* s_red = reinterpret_cast<float*>(sb[0]);    // 2016 floats < 4608
    switch (wid) {
        case 0:  stage_out<0>(acc, lid, s_red); break;
        case 1:  stage_out<1>(acc, lid, s_red); break;
        case 2:  stage_out<2>(acc, lid, s_red); break;
        default: stage_out<3>(acc, lid, s_red); break;
    }
    __syncthreads();

    float* ob = out + (size_t)b * PAIRS;
#pragma unroll 1
    for (int p = tid; p < PAIRS; p += THREADS)
        ob[p] = s_red[p];
}

extern "C" void kernel_launch(void* const* d_in, const int* in_sizes, int n_in,
                              void* d_out, int out_size) {
    const float* in = (const float*)d_in[0];
    float* out = (float*)d_out;
    (void)in_sizes; (void)n_in; (void)out_size;
    gram_mma_kernel<<<BATCH, THREADS>>>(in, out);
}

// round 16
// speedup vs baseline: 1.2376x; 1.0792x over previous
#include <cuda_runtime.h>
#include <cstdint>
#include <cstddef>

#define BATCH   4096
#define FFI     64
#define DDIM    256
#define PAIRS   2016
#define THREADS 128
#define KC      64                 // K elements per chunk
#define NCH     (DDIM / KC)        // 4
#define SROW    72                 // padded row stride (words), ==8 mod 32
#define BUF_WORDS (FFI * SROW)     // 4608 words = 18432 B per buffer

// Hybrid warp split: warp = (tg, kh). tg splits the 20 upper-triangular
// m16n8 tiles into two sets of 10 with minimal group unions; kh splits k in
// halves. Per global ks-step only 8+6=14 row-group loads happen (vs 20 for
// pure 4-way tile split). B frags alias A raw words (C = A*A^T).
__device__ constexpr int hMI[2][10] = {{0,0,0,0,0,0,0,0,3,3},
                                       {1,1,1,1,1,1,2,2,2,2}};
__device__ constexpr int hNJ[2][10] = {{0,1,2,3,4,5,6,7,6,7},
                                       {2,3,4,5,6,7,4,5,6,7}};
__device__ constexpr unsigned hMASK[2] = {0xFFu, 0xFCu};

__device__ __forceinline__ uint32_t f2tf32(float x) {
    uint32_t r;
    asm("cvt.rna.tf32.f32 %0, %1;" : "=r"(r) : "f"(x));
    return r;
}

__device__ __forceinline__ void mma8(float& d0, float& d1, float& d2, float& d3,
                                     uint32_t a0, uint32_t a1, uint32_t a2, uint32_t a3,
                                     uint32_t b0, uint32_t b1) {
    asm("mma.sync.aligned.m16n8k8.row.col.f32.tf32.tf32.f32 "
        "{%0,%1,%2,%3}, {%4,%5,%6,%7}, {%8,%9}, {%0,%1,%2,%3};"
        : "+f"(d0), "+f"(d1), "+f"(d2), "+f"(d3)
        : "r"(a0), "r"(a1), "r"(a2), "r"(a3), "r"(b0), "r"(b1));
}

__device__ __forceinline__ void cp_async16(uint32_t dst, const void* src) {
    asm volatile("cp.async.cg.shared.global [%0], [%1], 16;"
                 :: "r"(dst), "l"(src) : "memory");
}
__device__ __forceinline__ void cp_commit() {
    asm volatile("cp.async.commit_group;" ::: "memory");
}
__device__ __forceinline__ void cp_wait1() {
    asm volatile("cp.async.wait_group 1;" ::: "memory");
}

// One chunk for warp (TG, KH): 4 ks-steps in this warp's k-half. Per step,
// the masked row-groups are loaded once each (conflict-free LDS.64 at
// SROW==8 mod 32), cvt.rna'd to tf32, and feed this warp's 10 MMAs.
// Lane k-slots (2q, 2q+1) are a k-permutation applied identically to A and
// B fragments (same words, same mapping) -> k-sum unchanged.
template <int TG, int KH>
__device__ __forceinline__ void chunk_mma(const uint32_t* __restrict__ sb,
                                          int lid, float (&acc)[40]) {
    const int grp = lid >> 2, quad = lid & 3;
    const uint32_t* base = sb + grp * SROW + 2 * quad;
#pragma unroll
    for (int ks = 0; ks < 4; ks++) {
        const int k = KH * 32 + ks * 8;
        uint32_t c[8][2];
#pragma unroll
        for (int g = 0; g < 8; g++) {
            if (hMASK[TG] & (1u << g)) {
                uint2 v = *reinterpret_cast<const uint2*>(base + g * 8 * SROW + k);
                c[g][0] = f2tf32(__uint_as_float(v.x));
                c[g][1] = f2tf32(__uint_as_float(v.y));
            }
        }
#pragma unroll
        for (int t = 0; t < 10; t++) {
            const int a = 2 * hMI[TG][t], bj = hNJ[TG][t];
            mma8(acc[4 * t], acc[4 * t + 1], acc[4 * t + 2], acc[4 * t + 3],
                 c[a][0], c[a + 1][0], c[a][1], c[a + 1][1],
                 c[bj][0], c[bj][1]);
        }
    }
}

__device__ __forceinline__ void stg_pack(float* __restrict__ s_red, int i, int j,
                                         float v, bool need_check) {
    if (!need_check || j > i)
        s_red[i * FFI - (i * (i + 1)) / 2 + j - i - 1] = v;
}

template <int TG>
__device__ __forceinline__ void stage_out(const float (&acc)[40], int lid,
                                          float* __restrict__ s_red) {
    const int grp = lid >> 2, quad = lid & 3;
#pragma unroll
    for (int t = 0; t < 10; t++) {
        const int mi = hMI[TG][t], nj = hNJ[TG][t];
        const bool chk = (nj < 2 * mi + 2);   // tile straddles the diagonal
        const int i0 = mi * 16 + grp, i1 = i0 + 8;
        const int j0 = nj * 8 + 2 * quad, j1 = j0 + 1;
        stg_pack(s_red, i0, j0, acc[4 * t + 0], chk);
        stg_pack(s_red, i0, j1, acc[4 * t + 1], chk);
        stg_pack(s_red, i1, j0, acc[4 * t + 2], chk);
        stg_pack(s_red, i1, j1, acc[4 * t + 3], chk);
    }
}

__global__ void __launch_bounds__(THREADS, 5)
gram_hybrid_kernel(const float* __restrict__ in, float* __restrict__ out) {
    __shared__ __align__(16) uint32_t sb[2][BUF_WORDS];   // 36864 B

    const int tid = threadIdx.x;
    const int wid = tid >> 5, lid = tid & 31;
    const int b = blockIdx.x;

    const float* src = in + (size_t)b * (FFI * DDIM);
    uint32_t s0;
    asm("{ .reg .u64 t; cvta.to.shared.u64 t, %1; cvt.u32.u64 %0, t; }"
        : "=r"(s0) : "l"((const void*)sb));

    // cp.async one KC-chunk (raw fp32) into buffer (c&1). Always commits so
    // wait_group accounting stays uniform past the end.
    auto issue = [&](int c) {
        if (c < NCH) {
            const uint32_t dst = s0 + (uint32_t)((c & 1) * BUF_WORDS * 4);
            const float* sc = src + c * KC;
#pragma unroll
            for (int i = 0; i < 8; i++) {
                const int idx = tid + THREADS * i;
                const int r = idx >> 4, c4 = idx & 15;   // row, float4-col
                cp_async16(dst + (uint32_t)((r * SROW + c4 * 4) * 4),
                           sc + (size_t)r * DDIM + c4 * 4);
            }
        }
        cp_commit();
    };

    float acc[40];
#pragma unroll
    for (int i = 0; i < 40; i++) acc[i] = 0.0f;

    issue(0);
    issue(1);
    for (int c = 0; c < NCH; c++) {
        cp_wait1();            // chunk c landed (this thread's copies)
        __syncthreads();       // all threads' copies visible
        const uint32_t* buf = sb[c & 1];
        switch (wid) {         // wid -> (tg = wid&1, kh = wid>>1)
            case 0:  chunk_mma<0, 0>(buf, lid, acc); break;
            case 1:  chunk_mma<1, 0>(buf, lid, acc); break;
            case 2:  chunk_mma<0, 1>(buf, lid, acc); break;
            default: chunk_mma<1, 1>(buf, lid, acc); break;
        }
        __syncthreads();       // all reads of buf (c&1) done before rewrite
        issue(c + 2);
    }

    // ---- epilogue: per-k-half triangle-packed staging (16128 B, fits in
    // the dead buffers), then one coalesced add+store pass ----
    float* s_red = reinterpret_cast<float*>(sb);       // [2][PAIRS]
    switch (wid) {
        case 0:  stage_out<0>(acc, lid, s_red);         break;
        case 1:  stage_out<1>(acc, lid, s_red);         break;
        case 2:  stage_out<0>(acc, lid, s_red + PAIRS); break;
        default: stage_out<1>(acc, lid, s_red + PAIRS); break;
    }
    __syncthreads();

    float* ob = out + (size_t)b * PAIRS;
#pragma unroll 1
    for (int p = tid; p < PAIRS; p += THREADS)
        ob[p] = s_red[p] + s_red[PAIRS + p];
}

extern "C" void kernel_launch(void* const* d_in, const int* in_sizes, int n_in,
                              void* d_out, int out_size) {
    const float* in = (const float*)d_in[0];
    float* out = (float*)d_out;
    (void)in_sizes; (void)n_in; (void)out_size;
    gram_hybrid_kernel<<<BATCH, THREADS>>>(in, out);
}